// round 3
// baseline (speedup 1.0000x reference)
#include <cuda_runtime.h>
#include <cuda_bf16.h>
#include <cstdint>

#define N 4096
#define L 4096
#define TPB 256
#define MV_CTAS 128
#define GRID_TOT 129

// ---------------- device globals (no allocations allowed) ----------------
__device__ __nv_bfloat16 g_Tm[2][N][N];   // softmaxed transitions, bf16, [sym][from][to]
__device__ float         g_Om[2][N][4];   // softmaxed emissions, fp32, [sym][state][4]
__device__ float         g_x[2][N];       // double-buffered state vector
__device__ __align__(16) float g_partial[2][MV_CTAS];  // per-CTA sums of stored x, double-buffered
__device__ float         g_S0;            // true invariant sum(x0)
__device__ int           g_syms[L];
__device__ unsigned      g_arrive;
__device__ unsigned      g_release;

__device__ __forceinline__ float bf_lo(unsigned u) { return __uint_as_float(u << 16); }
__device__ __forceinline__ float bf_hi(unsigned u) { return __uint_as_float(u & 0xffff0000u); }

// ---------------- init: reset barrier, copy x0, partial sums, decode symbols ----------------
__global__ void init_kernel(const float* __restrict__ state_dist, const void* __restrict__ seq_raw) {
    __shared__ int s_sum;
    __shared__ float s_part[MV_CTAS];
    int tid = threadIdx.x;
    if (tid == 0) { s_sum = 0; g_arrive = 0u; g_release = 0u; }
    __syncthreads();
    // Detect int32 vs int64 storage of input_seq (values are 0/1).
    // If int64 (little-endian): odd 32-bit words are always 0. If int32: they are random 0/1.
    const int* w = (const int*)seq_raw;
    int local = 0;
    for (int j = tid; j < 2048; j += TPB) local += w[2 * j + 1];
    atomicAdd(&s_sum, local);
    __syncthreads();
    bool is64 = (s_sum == 0);
    for (int t = tid; t < L; t += TPB) {
        int v = is64 ? (int)((const long long*)seq_raw)[t] : w[t];
        g_syms[t] = v & 1;
    }
    for (int i = tid; i < N; i += TPB) g_x[0][i] = state_dist[i];
    // per-MV-CTA partial sums of x0 (32 entries each) + total S0
    if (tid < MV_CTAS) {
        float ps = 0.f;
        for (int j = 0; j < 32; j++) ps += state_dist[tid * 32 + j];
        g_partial[0][tid] = ps;
        s_part[tid] = ps;
    }
    __syncthreads();
    if (tid == 0) {
        float tot = 0.f;
        for (int bq = 0; bq < MV_CTAS; bq++) tot += s_part[bq];
        g_S0 = tot;
    }
}

// ---------------- softmax over T rows -> bf16 ----------------
__global__ void softmaxT_kernel(const float* __restrict__ T) {
    int r = blockIdx.x;           // 0..8191
    int i = r >> 1, s = r & 1;
    const float* row = T + ((size_t)(i * 2 + s)) * N;
    int tid = threadIdx.x;
    float v[16];
    float m = -1e30f;
#pragma unroll
    for (int k = 0; k < 16; k++) { v[k] = row[tid + k * TPB]; m = fmaxf(m, v[k]); }
#pragma unroll
    for (int o = 16; o > 0; o >>= 1) m = fmaxf(m, __shfl_xor_sync(0xffffffffu, m, o));
    __shared__ float sm[8];
    __shared__ float ss[8];
    if ((tid & 31) == 0) sm[tid >> 5] = m;
    __syncthreads();
    float mm = sm[0];
#pragma unroll
    for (int q = 1; q < 8; q++) mm = fmaxf(mm, sm[q]);
    float sum = 0.f;
#pragma unroll
    for (int k = 0; k < 16; k++) { v[k] = __expf(v[k] - mm); sum += v[k]; }
#pragma unroll
    for (int o = 16; o > 0; o >>= 1) sum += __shfl_xor_sync(0xffffffffu, sum, o);
    if ((tid & 31) == 0) ss[tid >> 5] = sum;
    __syncthreads();
    float st = 0.f;
#pragma unroll
    for (int q = 0; q < 8; q++) st += ss[q];
    float inv = 1.0f / st;
    __nv_bfloat16* dst = &g_Tm[s][i][0];
#pragma unroll
    for (int k = 0; k < 16; k++) dst[tid + k * TPB] = __float2bfloat16(v[k] * inv);
}

// ---------------- softmax over O rows (length 4) -> fp32 ----------------
__global__ void softmaxO_kernel(const float* __restrict__ O) {
    int r = blockIdx.x * blockDim.x + threadIdx.x;
    if (r >= 2 * N) return;
    int i = r >> 1, s = r & 1;
    const float* p = O + ((size_t)(i * 2 + s)) * 4;
    float a = p[0], b = p[1], c = p[2], d = p[3];
    float m = fmaxf(fmaxf(a, b), fmaxf(c, d));
    float ea = __expf(a - m), eb = __expf(b - m), ec = __expf(c - m), ed = __expf(d - m);
    float inv = 1.0f / (ea + eb + ec + ed);
    float4 o = make_float4(ea * inv, eb * inv, ec * inv, ed * inv);
    *(float4*)&g_Om[s][i][0] = o;
}

// ---------------- grid-wide barrier (all GRID_TOT CTAs co-resident) ----------------
__device__ __forceinline__ void grid_barrier(unsigned target) {
    __syncthreads();
    if (threadIdx.x == 0) {
        __threadfence();
        unsigned a = atomicAdd(&g_arrive, 1u);
        if (a == target * (unsigned)GRID_TOT - 1u) {
            atomicExch(&g_release, target);
        } else {
            volatile unsigned* rel = &g_release;
            while (*rel < target) { __nanosleep(64); }
            __threadfence();
        }
    }
    __syncthreads();
}

// factor = S0 / sum(g_partial[cur]); computed by warp 0, broadcast via smem.
// Deterministic: identical summation order in every CTA.
__device__ __forceinline__ void compute_factor(int cur, int tid, float* s_f) {
    if (tid < 32) {
        const float4* pp = (const float4*)&g_partial[cur][0];
        float4 p = __ldcg(&pp[tid]);          // 128 floats = 32 float4
        float v = (p.x + p.y) + (p.z + p.w);
#pragma unroll
        for (int o = 16; o > 0; o >>= 1) v += __shfl_xor_sync(0xffffffffu, v, o);
        if (tid == 0) *s_f = g_S0 / v;
    }
}

// ---------------- persistent forward-pass kernel ----------------
__global__ void __launch_bounds__(TPB, 1) hmm_kernel(float* __restrict__ out) {
    __shared__ float x_s[64 * 65];     // padded stride-65: conflict-free broadcast
    __shared__ float rbuf[64 * 33];    // [ig][col] partials, pad 33
    __shared__ float rbuf2[8 * 33];
    __shared__ float s_f;              // renormalization factor this step
    __shared__ float4 ored[TPB];       // output-CTA reduction

    const int b = blockIdx.x;
    const int tid = threadIdx.x;

    if (b < MV_CTAS) {
        const int cg = tid & 3;        // 4 column groups of 8 cols
        const int ig = tid >> 2;       // 64 i-groups of 64 rows
        const int jb = b * 32 + cg * 8;
        const int ibase = ig * 64;
        const uint4* base = (const uint4*)(&g_Tm[0][ibase][jb]);
        const size_t sym_stride = (size_t)N * N * 2 / 16;   // uint4 per symbol matrix
        const size_t row_stride = (size_t)N * 2 / 16;       // = 512 uint4 per row

        for (int t = 0; t < L; ++t) {
            const int cur = t & 1, nxt = cur ^ 1;
            const int s = g_syms[t];
            compute_factor(cur, tid, &s_f);    // warp 0 (also participates in staging)
            // stage x into smem (L2-scoped loads: other SMs wrote it)
            for (int idx = tid; idx < N; idx += TPB)
                x_s[(idx >> 6) * 65 + (idx & 63)] = __ldcg(&g_x[cur][idx]);
            __syncthreads();

            float acc[8];
#pragma unroll
            for (int m = 0; m < 8; m++) acc[m] = 0.f;
            const uint4* bp = base + (size_t)s * sym_stride;
            const float* xl = &x_s[ig * 65];
#pragma unroll 4
            for (int k = 0; k < 64; ++k) {
                float xv = xl[k];
                uint4 w = bp[(size_t)k * row_stride];
                acc[0] += xv * bf_lo(w.x); acc[1] += xv * bf_hi(w.x);
                acc[2] += xv * bf_lo(w.y); acc[3] += xv * bf_hi(w.y);
                acc[4] += xv * bf_lo(w.z); acc[5] += xv * bf_hi(w.z);
                acc[6] += xv * bf_lo(w.w); acc[7] += xv * bf_hi(w.w);
            }
#pragma unroll
            for (int m = 0; m < 8; m++) rbuf[ig * 33 + cg * 8 + m] = acc[m];
            __syncthreads();
            {
                int col = tid & 31, g8 = tid >> 5;
                float v2 = 0.f;
#pragma unroll
                for (int m2 = 0; m2 < 8; m2++) v2 += rbuf[(g8 * 8 + m2) * 33 + col];
                rbuf2[g8 * 33 + col] = v2;
            }
            __syncthreads();
            if (tid < 32) {
                float y = 0.f;
#pragma unroll
                for (int g8 = 0; g8 < 8; g8++) y += rbuf2[g8 * 33 + tid];
                y *= s_f;                               // renormalize: kills mass drift
                __stcg(&g_x[nxt][b * 32 + tid], y);
                // publish this CTA's partial sum of the stored vector
                float ps = y;
#pragma unroll
                for (int o = 16; o > 0; o >>= 1) ps += __shfl_xor_sync(0xffffffffu, ps, o);
                if (tid == 0) __stcg(&g_partial[nxt][b], ps);
            }
            grid_barrier((unsigned)(t + 1));
        }
    } else {
        // emission CTA: out[t] = (f * x_t) @ Om[s_t]
        for (int t = 0; t < L; ++t) {
            const int cur = t & 1;
            const int s = g_syms[t];
            compute_factor(cur, tid, &s_f);
            float4 a = make_float4(0.f, 0.f, 0.f, 0.f);
            for (int idx = tid; idx < N; idx += TPB) {
                float xv = __ldcg(&g_x[cur][idx]);
                float4 om = *(const float4*)&g_Om[s][idx][0];
                a.x += xv * om.x; a.y += xv * om.y; a.z += xv * om.z; a.w += xv * om.w;
            }
            ored[tid] = a;
            __syncthreads();
            for (int off = TPB / 2; off > 0; off >>= 1) {
                if (tid < off) {
                    float4 o2 = ored[tid + off];
                    float4 m = ored[tid];
                    m.x += o2.x; m.y += o2.y; m.z += o2.z; m.w += o2.w;
                    ored[tid] = m;
                }
                __syncthreads();
            }
            if (tid == 0) {
                float4 r = ored[0];
                float f = s_f;
                r.x *= f; r.y *= f; r.z *= f; r.w *= f;
                *(float4*)&out[(size_t)t * 4] = r;
            }
            grid_barrier((unsigned)(t + 1));
        }
    }
}

// ---------------- launch ----------------
extern "C" void kernel_launch(void* const* d_in, const int* in_sizes, int n_in,
                              void* d_out, int out_size) {
    const float* state_dist = (const float*)d_in[0];
    const void*  seq        = d_in[1];
    const float* T          = (const float*)d_in[2];
    const float* O          = (const float*)d_in[3];
    float* out = (float*)d_out;

    init_kernel<<<1, TPB>>>(state_dist, seq);
    softmaxT_kernel<<<2 * N, TPB>>>(T);
    softmaxO_kernel<<<(2 * N + TPB - 1) / TPB, TPB>>>(O);
    hmm_kernel<<<GRID_TOT, TPB>>>(out);
}

// round 7
// speedup vs baseline: 1.3942x; 1.3942x over previous
#include <cuda_runtime.h>
#include <cuda_bf16.h>
#include <cstdint>

#define N 4096
#define L 4096
#define TPB 256      // init/softmax kernels
#define TPB_MV 512   // persistent kernel
#define MV_CTAS 128
#define GRID_TOT 129

// ---------------- device globals (no allocations allowed) ----------------
// Packed transitions: each MV CTA's 32-col slice stored contiguously (256KB/slice)
__device__ __nv_bfloat16 g_Tp[2][MV_CTAS][N][32];
__device__ float         g_Om[2][N][4];   // softmaxed emissions, fp32
__device__ float         g_x[2][N];       // double-buffered state vector
__device__ __align__(16) float g_partial[2][MV_CTAS];
__device__ float         g_S0;
__device__ int           g_syms[L];
__device__ unsigned      g_arrive;
__device__ unsigned      g_release;

__device__ __forceinline__ float bf_lo(unsigned u) { return __uint_as_float(u << 16); }
__device__ __forceinline__ float bf_hi(unsigned u) { return __uint_as_float(u & 0xffff0000u); }

// ---------------- init ----------------
__global__ void init_kernel(const float* __restrict__ state_dist, const void* __restrict__ seq_raw) {
    __shared__ int s_sum;
    __shared__ float s_part[MV_CTAS];
    int tid = threadIdx.x;
    if (tid == 0) { s_sum = 0; g_arrive = 0u; g_release = 0u; }
    __syncthreads();
    // int32 vs int64 detection (values 0/1; int64 odd words always 0)
    const int* w = (const int*)seq_raw;
    int local = 0;
    for (int j = tid; j < 2048; j += TPB) local += w[2 * j + 1];
    atomicAdd(&s_sum, local);
    __syncthreads();
    bool is64 = (s_sum == 0);
    for (int t = tid; t < L; t += TPB) {
        int v = is64 ? (int)((const long long*)seq_raw)[t] : w[t];
        g_syms[t] = v & 1;
    }
    for (int i = tid; i < N; i += TPB) g_x[0][i] = state_dist[i];
    if (tid < MV_CTAS) {
        float ps = 0.f;
        for (int j = 0; j < 32; j++) ps += state_dist[tid * 32 + j];
        g_partial[0][tid] = ps;
        s_part[tid] = ps;
    }
    __syncthreads();
    if (tid == 0) {
        float tot = 0.f;
        for (int bq = 0; bq < MV_CTAS; bq++) tot += s_part[bq];
        g_S0 = tot;
    }
}

// ---------------- softmax over T rows -> packed bf16 ----------------
// One CTA per (state,sym) row. Thread tid handles 16 consecutive cols.
__global__ void softmaxT_kernel(const float* __restrict__ T) {
    int r = blockIdx.x;           // 0..8191
    int i = r >> 1, s = r & 1;
    const float4* row = (const float4*)(T + ((size_t)(i * 2 + s)) * N);
    int tid = threadIdx.x;        // 256
    float4 v4[4];
    float m = -1e30f;
#pragma unroll
    for (int k = 0; k < 4; k++) {
        v4[k] = row[tid * 4 + k];
        m = fmaxf(m, fmaxf(fmaxf(v4[k].x, v4[k].y), fmaxf(v4[k].z, v4[k].w)));
    }
#pragma unroll
    for (int o = 16; o > 0; o >>= 1) m = fmaxf(m, __shfl_xor_sync(0xffffffffu, m, o));
    __shared__ float sm[8];
    __shared__ float ss[8];
    if ((tid & 31) == 0) sm[tid >> 5] = m;
    __syncthreads();
    float mm = sm[0];
#pragma unroll
    for (int q = 1; q < 8; q++) mm = fmaxf(mm, sm[q]);
    float e[16];
    float sum = 0.f;
#pragma unroll
    for (int k = 0; k < 4; k++) {
        float* p = (float*)&v4[k];
#pragma unroll
        for (int c = 0; c < 4; c++) { float ev = __expf(p[c] - mm); e[k * 4 + c] = ev; sum += ev; }
    }
#pragma unroll
    for (int o = 16; o > 0; o >>= 1) sum += __shfl_xor_sync(0xffffffffu, sum, o);
    if ((tid & 31) == 0) ss[tid >> 5] = sum;
    __syncthreads();
    float st = 0.f;
#pragma unroll
    for (int q = 0; q < 8; q++) st += ss[q];
    float inv = 1.0f / st;
    unsigned pk[8];
#pragma unroll
    for (int k = 0; k < 8; k++) {
        __nv_bfloat162 b2 = __float22bfloat162_rn(make_float2(e[2 * k] * inv, e[2 * k + 1] * inv));
        pk[k] = *(unsigned*)&b2;
    }
    int cb = tid >> 1;            // colblock 0..127
    int half = tid & 1;           // 16-col half within the 32-col block
    uint4* dst = (uint4*)&g_Tp[s][cb][i][half * 16];
    dst[0] = make_uint4(pk[0], pk[1], pk[2], pk[3]);
    dst[1] = make_uint4(pk[4], pk[5], pk[6], pk[7]);
}

// ---------------- softmax over O rows ----------------
__global__ void softmaxO_kernel(const float* __restrict__ O) {
    int r = blockIdx.x * blockDim.x + threadIdx.x;
    if (r >= 2 * N) return;
    int i = r >> 1, s = r & 1;
    const float* p = O + ((size_t)(i * 2 + s)) * 4;
    float a = p[0], b = p[1], c = p[2], d = p[3];
    float m = fmaxf(fmaxf(a, b), fmaxf(c, d));
    float ea = __expf(a - m), eb = __expf(b - m), ec = __expf(c - m), ed = __expf(d - m);
    float inv = 1.0f / (ea + eb + ec + ed);
    *(float4*)&g_Om[s][i][0] = make_float4(ea * inv, eb * inv, ec * inv, ed * inv);
}

// ---------------- grid-wide barrier: bounded spin, then nanosleep backoff ----------------
__device__ __forceinline__ void grid_barrier(unsigned target) {
    __syncthreads();
    if (threadIdx.x == 0) {
        __threadfence();
        unsigned a = atomicAdd(&g_arrive, 1u);
        if (a == target * (unsigned)GRID_TOT - 1u) {
            atomicExch(&g_release, target);
        } else {
            volatile unsigned* rel = &g_release;
            int spins = 0;
            while (*rel < target) {
                if (++spins > 512) { __nanosleep(32); spins = 0; }
            }
            __threadfence();
        }
    }
    __syncthreads();
}

// factor = S0 / sum(g_partial[cur]); warp 0 computes, broadcasts via smem
__device__ __forceinline__ void compute_factor(int cur, int tid, float* s_f) {
    if (tid < 32) {
        const float4* pp = (const float4*)&g_partial[cur][0];
        float4 p = __ldcg(&pp[tid]);
        float v = (p.x + p.y) + (p.z + p.w);
#pragma unroll
        for (int o = 16; o > 0; o >>= 1) v += __shfl_xor_sync(0xffffffffu, v, o);
        if (tid == 0) *s_f = g_S0 / v;
    }
}

// ---------------- persistent forward-pass kernel ----------------
__global__ void __launch_bounds__(TPB_MV, 1) hmm_kernel(float* __restrict__ out) {
    __shared__ float x_s[64 * 65];       // padded: conflict-free broadcast
    __shared__ float rbuf[128 * 33];     // [ig][col] partials
    __shared__ float rbuf2[16 * 33];
    __shared__ float s_f;
    __shared__ float4 ored[TPB_MV];      // emission reduction

    const int b = blockIdx.x;
    const int tid = threadIdx.x;

    if (b < MV_CTAS) {
        const int cg = tid & 3;          // 4 col groups of 8 cols
        const int ig = tid >> 2;         // 128 row groups (rows ig + 128*i)
        const int xbase = (ig >> 6) * 65 + (ig & 63);   // advances by 130 per i
        const uint4* slice0 = (const uint4*)g_Tp + (size_t)b * 16384 + tid;
        const size_t sym_stride = (size_t)MV_CTAS * 16384;

        for (int t = 0; t < L; ++t) {
            const int cur = t & 1, nxt = cur ^ 1;
            const int s = __ldg(&g_syms[t]);
            compute_factor(cur, tid, &s_f);
            for (int idx = tid; idx < N; idx += TPB_MV)
                x_s[(idx >> 6) * 65 + (idx & 63)] = __ldcg(&g_x[cur][idx]);
            __syncthreads();

            float acc[8];
#pragma unroll
            for (int m = 0; m < 8; m++) acc[m] = 0.f;
            const uint4* bp = slice0 + (size_t)s * sym_stride;
#pragma unroll 8
            for (int i = 0; i < 32; ++i) {
                float xv = x_s[xbase + 130 * i];
                uint4 w = __ldcg(&bp[i * 512]);          // fully coalesced 512B/warp
                acc[0] += xv * bf_lo(w.x); acc[1] += xv * bf_hi(w.x);
                acc[2] += xv * bf_lo(w.y); acc[3] += xv * bf_hi(w.y);
                acc[4] += xv * bf_lo(w.z); acc[5] += xv * bf_hi(w.z);
                acc[6] += xv * bf_lo(w.w); acc[7] += xv * bf_hi(w.w);
            }
#pragma unroll
            for (int m = 0; m < 8; m++) rbuf[ig * 33 + cg * 8 + m] = acc[m];
            __syncthreads();
            {
                int col = tid & 31, c = tid >> 5;        // 16 chunks of 8 ig
                float v2 = 0.f;
#pragma unroll
                for (int m2 = 0; m2 < 8; m2++) v2 += rbuf[(c * 8 + m2) * 33 + col];
                rbuf2[c * 33 + col] = v2;
            }
            __syncthreads();
            if (tid < 32) {
                float y = 0.f;
#pragma unroll
                for (int c = 0; c < 16; c++) y += rbuf2[c * 33 + tid];
                y *= s_f;                                // renormalize mass
                __stcg(&g_x[nxt][b * 32 + tid], y);
                float ps = y;
#pragma unroll
                for (int o = 16; o > 0; o >>= 1) ps += __shfl_xor_sync(0xffffffffu, ps, o);
                if (tid == 0) __stcg(&g_partial[nxt][b], ps);
            }
            grid_barrier((unsigned)(t + 1));
        }
    } else {
        // emission CTA
        for (int t = 0; t < L; ++t) {
            const int cur = t & 1;
            const int s = __ldg(&g_syms[t]);
            compute_factor(cur, tid, &s_f);
            float4 a = make_float4(0.f, 0.f, 0.f, 0.f);
            for (int idx = tid; idx < N; idx += TPB_MV) {
                float xv = __ldcg(&g_x[cur][idx]);
                float4 om = *(const float4*)&g_Om[s][idx][0];
                a.x += xv * om.x; a.y += xv * om.y; a.z += xv * om.z; a.w += xv * om.w;
            }
            ored[tid] = a;
            __syncthreads();
            for (int off = TPB_MV / 2; off > 0; off >>= 1) {
                if (tid < off) {
                    float4 o2 = ored[tid + off];
                    float4 m = ored[tid];
                    m.x += o2.x; m.y += o2.y; m.z += o2.z; m.w += o2.w;
                    ored[tid] = m;
                }
                __syncthreads();
            }
            if (tid == 0) {
                float4 r = ored[0];
                float f = s_f;
                r.x *= f; r.y *= f; r.z *= f; r.w *= f;
                *(float4*)&out[(size_t)t * 4] = r;
            }
            grid_barrier((unsigned)(t + 1));
        }
    }
}

// ---------------- launch ----------------
extern "C" void kernel_launch(void* const* d_in, const int* in_sizes, int n_in,
                              void* d_out, int out_size) {
    const float* state_dist = (const float*)d_in[0];
    const void*  seq        = d_in[1];
    const float* T          = (const float*)d_in[2];
    const float* O          = (const float*)d_in[3];
    float* out = (float*)d_out;

    init_kernel<<<1, TPB>>>(state_dist, seq);
    softmaxT_kernel<<<2 * N, TPB>>>(T);
    softmaxO_kernel<<<(2 * N + TPB - 1) / TPB, TPB>>>(O);
    hmm_kernel<<<GRID_TOT, TPB_MV>>>(out);
}